// round 7
// baseline (speedup 1.0000x reference)
#include <cuda_runtime.h>
#include <cuda_bf16.h>
#include <cstdint>

#define B_   4096
#define G_   8
#define IN_  512
#define H_   1024
#define OUT_ 64

#define TM1    64
#define MAXT1  (B_ / TM1 + G_)   // 72
#define TM2    128
#define MAXT2  (B_ / TM2 + G_)   // 40
#define NSPLIT 4

// ---------------- gemm1 smem layout (per stage, bytes) ----------------
// A: 64 rows x 32k bf16, stride 80B.  B: 32 k-rows x 128n, stride 272B
#define S1_A_HI 0
#define S1_A_LO 5120
#define S1_B_HI 10240
#define S1_B_LO 18944
#define STAGE1  27648
#define SMEM1   (2 * STAGE1)     // 55296; x4 CTAs = 221184 <= 228KB/SM

// ---------------- gemm2 smem layout ----------------
#define S2_A_HI 0
#define S2_A_LO 10240
#define S2_B_HI 20480
#define S2_B_LO 25088
#define STAGE2  29696
#define SMEM2   (2 * STAGE2)

// ---------------- device scratch ----------------
__device__ int d_offsets[G_ + 1];
__device__ int d_cursor[G_];
__device__ int d_perm[B_];
__device__ int d_rowg[B_];
__device__ int t1_group[MAXT1], t1_start[MAXT1], t1_end[MAXT1];
__device__ int t2_group[MAXT2], t2_start[MAXT2], t2_end[MAXT2];

__device__ __nv_bfloat16 d_xhi[(size_t)B_ * IN_];
__device__ __nv_bfloat16 d_xlo[(size_t)B_ * IN_];
__device__ __nv_bfloat16 d_w1hi[(size_t)G_ * IN_ * H_];
__device__ __nv_bfloat16 d_w1lo[(size_t)G_ * IN_ * H_];
__device__ __nv_bfloat16 d_w2hi[(size_t)G_ * H_ * OUT_];
__device__ __nv_bfloat16 d_w2lo[(size_t)G_ * H_ * OUT_];
__device__ __nv_bfloat16 d_hhi[(size_t)B_ * H_];
__device__ __nv_bfloat16 d_hlo[(size_t)B_ * H_];
__device__ float d_ypart[(size_t)NSPLIT * B_ * OUT_];

// ---------------- asm helpers ----------------
__device__ __forceinline__ uint32_t smem_u32(const void* p) {
    uint32_t a;
    asm("{ .reg .u64 t; cvta.to.shared.u64 t, %1; cvt.u32.u64 %0, t; }" : "=r"(a) : "l"(p));
    return a;
}
__device__ __forceinline__ void cp16(uint32_t s, const void* g, int srcsz) {
    asm volatile("cp.async.cg.shared.global [%0], [%1], 16, %2;"
                 :: "r"(s), "l"(g), "r"(srcsz) : "memory");
}
#define CP_COMMIT() asm volatile("cp.async.commit_group;" ::: "memory")
#define CP_WAIT1()  asm volatile("cp.async.wait_group 1;" ::: "memory")
#define CP_WAIT0()  asm volatile("cp.async.wait_group 0;" ::: "memory")

#define LDSM_X4(r, a)                                                            \
    asm volatile("ldmatrix.sync.aligned.m8n8.x4.shared.b16 {%0,%1,%2,%3}, [%4];" \
                 : "=r"((r)[0]), "=r"((r)[1]), "=r"((r)[2]), "=r"((r)[3]) : "r"(a))
#define LDSM_X4T(r, a)                                                                 \
    asm volatile("ldmatrix.sync.aligned.m8n8.x4.trans.shared.b16 {%0,%1,%2,%3}, [%4];" \
                 : "=r"((r)[0]), "=r"((r)[1]), "=r"((r)[2]), "=r"((r)[3]) : "r"(a))

#define MMA16816(c, a, b0, b1)                                                    \
    asm volatile("mma.sync.aligned.m16n8k16.row.col.f32.bf16.bf16.f32 "           \
                 "{%0,%1,%2,%3}, {%4,%5,%6,%7}, {%8,%9}, {%0,%1,%2,%3};"          \
                 : "+f"((c)[0]), "+f"((c)[1]), "+f"((c)[2]), "+f"((c)[3])         \
                 : "r"((a)[0]), "r"((a)[1]), "r"((a)[2]), "r"((a)[3]),            \
                   "r"(b0), "r"(b1))

__device__ __forceinline__ uint32_t pack_hi2(float a, float b) {
    __nv_bfloat162 t = __floats2bfloat162_rn(a, b);
    return *reinterpret_cast<uint32_t*>(&t);
}
__device__ __forceinline__ void split8(const float* v, uint4& hi, uint4& lo) {
    float h[8], l[8];
#pragma unroll
    for (int i = 0; i < 8; i++) {
        __nv_bfloat16 bh = __float2bfloat16_rn(v[i]);
        h[i] = __bfloat162float(bh);
        l[i] = v[i] - h[i];
    }
    hi = make_uint4(pack_hi2(h[0], h[1]), pack_hi2(h[2], h[3]),
                    pack_hi2(h[4], h[5]), pack_hi2(h[6], h[7]));
    lo = make_uint4(pack_hi2(l[0], l[1]), pack_hi2(l[2], l[3]),
                    pack_hi2(l[4], l[5]), pack_hi2(l[6], l[7]));
}

// ---------------- routing ----------------
__global__ void k_count_plan(const int* __restrict__ gid) {
    __shared__ int hist[G_];
    int tid = threadIdx.x;
    if (tid < G_) hist[tid] = 0;
    __syncthreads();
    for (int i = tid; i < B_; i += 256) atomicAdd(&hist[gid[i]], 1);
    __syncthreads();
    if (tid == 0) {
        int off = 0;
        d_offsets[0] = 0;
        for (int g = 0; g < G_; g++) {
            off += hist[g];
            d_offsets[g + 1] = off;
            d_cursor[g] = d_offsets[g];
        }
        int t = 0;
        for (int g = 0; g < G_; g++)
            for (int r = d_offsets[g]; r < d_offsets[g + 1]; r += TM1) {
                t1_group[t] = g; t1_start[t] = r;
                t1_end[t] = min(r + TM1, d_offsets[g + 1]);
                t++;
            }
        for (; t < MAXT1; t++) t1_group[t] = -1;
        t = 0;
        for (int g = 0; g < G_; g++)
            for (int r = d_offsets[g]; r < d_offsets[g + 1]; r += TM2) {
                t2_group[t] = g; t2_start[t] = r;
                t2_end[t] = min(r + TM2, d_offsets[g + 1]);
                t++;
            }
        for (; t < MAXT2; t++) t2_group[t] = -1;
    }
}

__global__ void k_scatter(const int* __restrict__ gid) {
    int i = blockIdx.x * blockDim.x + threadIdx.x;
    if (i < B_) {
        int g = gid[i];
        int p = atomicAdd(&d_cursor[g], 1);
        d_perm[p] = i;
        d_rowg[p] = g;
    }
}

// ---------------- merged converter (fp32 -> bf16 hi/lo), 16 elems/thread ----
#define CVT_XB  512
#define CVT_W1B 1024
#define CVT_W2B 128
#define CVT_NB  (CVT_XB + CVT_W1B + CVT_W2B)

__device__ __forceinline__ void cvt16(const float* __restrict__ src, size_t soff,
                                      __nv_bfloat16* dhi, __nv_bfloat16* dlo, size_t doff) {
    const float4* p = reinterpret_cast<const float4*>(src + soff);
    float4 q0 = p[0], q1 = p[1], q2 = p[2], q3 = p[3];
    float v0[8] = {q0.x, q0.y, q0.z, q0.w, q1.x, q1.y, q1.z, q1.w};
    float v1[8] = {q2.x, q2.y, q2.z, q2.w, q3.x, q3.y, q3.z, q3.w};
    uint4 h0, l0, h1, l1;
    split8(v0, h0, l0);
    split8(v1, h1, l1);
    uint4* ph = reinterpret_cast<uint4*>(dhi + doff);
    uint4* pl = reinterpret_cast<uint4*>(dlo + doff);
    ph[0] = h0; ph[1] = h1;
    pl[0] = l0; pl[1] = l1;
}

__global__ __launch_bounds__(256) void k_convert(const float* __restrict__ x,
                                                 const float* __restrict__ W1,
                                                 const float* __restrict__ W2) {
    int b = blockIdx.x;
    int tid = threadIdx.x;
    if (b < CVT_XB) {
        int u = b * 256 + tid;
        int p = u >> 5;
        int k = (u & 31) * 16;
        int src = d_perm[p];
        cvt16(x, (size_t)src * IN_ + k, d_xhi, d_xlo, (size_t)p * IN_ + k);
    } else if (b < CVT_XB + CVT_W1B) {
        size_t u = (size_t)(b - CVT_XB) * 256 + tid;
        cvt16(W1, u * 16, d_w1hi, d_w1lo, u * 16);
    } else {
        size_t u = (size_t)(b - CVT_XB - CVT_W1B) * 256 + tid;
        cvt16(W2, u * 16, d_w2hi, d_w2lo, u * 16);
    }
}

// ---------------- gemm1: h = relu(x @ W1[g] + b1[g]) ----------------
// 64x128 tile, 128 threads, 4 CTAs/SM -> 576 CTAs, single wave
__global__ __launch_bounds__(128, 4) void k_gemm1(const float* __restrict__ b1) {
    int tile = blockIdx.x;
    int g = t1_group[tile];
    if (g < 0) return;
    int rs = t1_start[tile], re = t1_end[tile];
    int n0 = blockIdx.y * 128;

    extern __shared__ char sm[];
    uint32_t smb = smem_u32(sm);
    int tid = threadIdx.x;
    int lane = tid & 31;
    int wid = tid >> 5;
    int warp_m = wid >> 1, warp_n = wid & 1;

    const __nv_bfloat16* w1hi = d_w1hi + (size_t)g * IN_ * H_;
    const __nv_bfloat16* w1lo = d_w1lo + (size_t)g * IN_ * H_;

#define STAGE_G1(bi, ch) do {                                                    \
    int k0 = (ch) * 32;                                                          \
    uint32_t sb = smb + (bi) * STAGE1;                                           \
    _Pragma("unroll")                                                            \
    for (int j = 0; j < 2; j++) {                                                \
        int c = tid + 128 * j;                                                   \
        int row = c >> 2, seg = c & 3;                                           \
        int gr = rs + row;                                                       \
        int ok = (gr < re) ? 16 : 0;                                             \
        size_t go = (size_t)(ok ? gr : rs) * IN_ + k0 + seg * 8;                 \
        uint32_t so = row * 80 + seg * 16;                                       \
        cp16(sb + S1_A_HI + so, d_xhi + go, ok);                                 \
        cp16(sb + S1_A_LO + so, d_xlo + go, ok);                                 \
    }                                                                            \
    _Pragma("unroll")                                                            \
    for (int j = 0; j < 4; j++) {                                                \
        int c = tid + 128 * j;                                                   \
        int row = c >> 4, seg = c & 15;                                          \
        size_t go = (size_t)(k0 + row) * H_ + n0 + seg * 8;                      \
        uint32_t so = row * 272 + seg * 16;                                      \
        cp16(sb + S1_B_HI + so, w1hi + go, 16);                                  \
        cp16(sb + S1_B_LO + so, w1lo + go, 16);                                  \
    }                                                                            \
} while (0)

    float acc[2][8][4];
#pragma unroll
    for (int t = 0; t < 2; t++)
#pragma unroll
        for (int n = 0; n < 8; n++)
#pragma unroll
            for (int r = 0; r < 4; r++) acc[t][n][r] = 0.f;

    STAGE_G1(0, 0);
    CP_COMMIT();

    const int NCH = IN_ / 32;   // 16
    for (int ch = 0; ch < NCH; ch++) {
        if (ch + 1 < NCH) { STAGE_G1((ch + 1) & 1, ch + 1); CP_COMMIT(); CP_WAIT1(); }
        else CP_WAIT0();
        __syncthreads();

        uint32_t sb = smb + (ch & 1) * STAGE1;
#pragma unroll
        for (int kk = 0; kk < 2; kk++) {
            uint32_t ah[2][4], al[2][4];
#pragma unroll
            for (int t = 0; t < 2; t++) {
                uint32_t ao = (warp_m * 32 + t * 16 + (lane & 15)) * 80
                            + kk * 32 + (lane >> 4) * 16;
                LDSM_X4(ah[t], sb + S1_A_HI + ao);
                LDSM_X4(al[t], sb + S1_A_LO + ao);
            }
#pragma unroll
            for (int q = 0; q < 4; q++) {
                uint32_t bh[4], bl[4];
                uint32_t bo = (kk * 16 + (lane & 15)) * 272
                            + (warp_n * 64 + q * 16) * 2 + (lane >> 4) * 16;
                LDSM_X4T(bh, sb + S1_B_HI + bo);
                LDSM_X4T(bl, sb + S1_B_LO + bo);
                int n0q = q * 2;
#pragma unroll
                for (int t = 0; t < 2; t++) {
                    MMA16816(acc[t][n0q],     ah[t], bh[0], bh[1]);
                    MMA16816(acc[t][n0q + 1], ah[t], bh[2], bh[3]);
                }
#pragma unroll
                for (int t = 0; t < 2; t++) {
                    MMA16816(acc[t][n0q],     ah[t], bl[0], bl[1]);
                    MMA16816(acc[t][n0q + 1], ah[t], bl[2], bl[3]);
                }
#pragma unroll
                for (int t = 0; t < 2; t++) {
                    MMA16816(acc[t][n0q],     al[t], bh[0], bh[1]);
                    MMA16816(acc[t][n0q + 1], al[t], bh[2], bh[3]);
                }
            }
        }
        __syncthreads();
    }
#undef STAGE_G1

    // epilogue: bias + relu, split into h hi/lo
    const float* b1g = b1 + g * H_;
#pragma unroll
    for (int n = 0; n < 8; n++) {
        int col = n0 + warp_n * 64 + n * 8 + (lane & 3) * 2;
        float bb0 = __ldg(b1g + col), bb1 = __ldg(b1g + col + 1);
#pragma unroll
        for (int t = 0; t < 2; t++) {
            int r0 = rs + warp_m * 32 + t * 16 + (lane >> 2);
            if (r0 < re) {
                float v0 = fmaxf(acc[t][n][0] + bb0, 0.f);
                float v1 = fmaxf(acc[t][n][1] + bb1, 0.f);
                float h0 = __bfloat162float(__float2bfloat16_rn(v0));
                float h1 = __bfloat162float(__float2bfloat16_rn(v1));
                *reinterpret_cast<uint32_t*>(d_hhi + (size_t)r0 * H_ + col) = pack_hi2(h0, h1);
                *reinterpret_cast<uint32_t*>(d_hlo + (size_t)r0 * H_ + col) = pack_hi2(v0 - h0, v1 - h1);
            }
            int r1 = r0 + 8;
            if (r1 < re) {
                float v0 = fmaxf(acc[t][n][2] + bb0, 0.f);
                float v1 = fmaxf(acc[t][n][3] + bb1, 0.f);
                float h0 = __bfloat162float(__float2bfloat16_rn(v0));
                float h1 = __bfloat162float(__float2bfloat16_rn(v1));
                *reinterpret_cast<uint32_t*>(d_hhi + (size_t)r1 * H_ + col) = pack_hi2(h0, h1);
                *reinterpret_cast<uint32_t*>(d_hlo + (size_t)r1 * H_ + col) = pack_hi2(v0 - h0, v1 - h1);
            }
        }
    }
}

// ---------------- gemm2: ypart = h @ W2[g] (split-K) ----------------
__global__ __launch_bounds__(256, 2) void k_gemm2() {
    int tile = blockIdx.x;
    int g = t2_group[tile];
    if (g < 0) return;
    int rs = t2_start[tile], re = t2_end[tile];
    int kcs = blockIdx.y;
    int kb = kcs * (H_ / NSPLIT);

    extern __shared__ char sm[];
    uint32_t smb = smem_u32(sm);
    int tid = threadIdx.x;
    int lane = tid & 31;
    int wid = tid >> 5;

    const __nv_bfloat16* w2hi = d_w2hi + (size_t)g * H_ * OUT_;
    const __nv_bfloat16* w2lo = d_w2lo + (size_t)g * H_ * OUT_;

#define STAGE_G2(bi, ch) do {                                                    \
    int k0 = kb + (ch) * 32;                                                     \
    uint32_t sb = smb + (bi) * STAGE2;                                           \
    _Pragma("unroll")                                                            \
    for (int j = 0; j < 2; j++) {                                                \
        int c = tid + 256 * j;                                                   \
        int row = c >> 2, seg = c & 3;                                           \
        int gr = rs + row;                                                       \
        int ok = (gr < re) ? 16 : 0;                                             \
        size_t go = (size_t)(ok ? gr : rs) * H_ + k0 + seg * 8;                  \
        uint32_t so = row * 80 + seg * 16;                                       \
        cp16(sb + S2_A_HI + so, d_hhi + go, ok);                                 \
        cp16(sb + S2_A_LO + so, d_hlo + go, ok);                                 \
    }                                                                            \
    {                                                                            \
        int row = tid >> 3, seg = tid & 7;                                       \
        size_t go = (size_t)(k0 + row) * OUT_ + seg * 8;                         \
        uint32_t so = row * 144 + seg * 16;                                      \
        cp16(sb + S2_B_HI + so, w2hi + go, 16);                                  \
        cp16(sb + S2_B_LO + so, w2lo + go, 16);                                  \
    }                                                                            \
} while (0)

    float acc[8][4];
#pragma unroll
    for (int n = 0; n < 8; n++)
#pragma unroll
        for (int r = 0; r < 4; r++) acc[n][r] = 0.f;

    STAGE_G2(0, 0);
    CP_COMMIT();

    const int NCH = (H_ / NSPLIT) / 32;   // 8
    for (int ch = 0; ch < NCH; ch++) {
        if (ch + 1 < NCH) { STAGE_G2((ch + 1) & 1, ch + 1); CP_COMMIT(); CP_WAIT1(); }
        else CP_WAIT0();
        __syncthreads();

        uint32_t sb = smb + (ch & 1) * STAGE2;
#pragma unroll
        for (int kk = 0; kk < 2; kk++) {
            uint32_t ah[4], al[4];
            uint32_t ao = (wid * 16 + (lane & 15)) * 80 + kk * 32 + (lane >> 4) * 16;
            LDSM_X4(ah, sb + S2_A_HI + ao);
            LDSM_X4(al, sb + S2_A_LO + ao);
#pragma unroll
            for (int q = 0; q < 4; q++) {
                uint32_t bh[4], bl[4];
                uint32_t bo = (kk * 16 + (lane & 15)) * 144 + q * 32 + (lane >> 4) * 16;
                LDSM_X4T(bh, sb + S2_B_HI + bo);
                LDSM_X4T(bl, sb + S2_B_LO + bo);
                int n0q = q * 2;
                MMA16816(acc[n0q],     ah, bh[0], bh[1]);
                MMA16816(acc[n0q + 1], ah, bh[2], bh[3]);
                MMA16816(acc[n0q],     ah, bl[0], bl[1]);
                MMA16816(acc[n0q + 1], ah, bl[2], bl[3]);
                MMA16816(acc[n0q],     al, bh[0], bh[1]);
                MMA16816(acc[n0q + 1], al, bh[2], bh[3]);
            }
        }
        __syncthreads();
    }
#undef STAGE_G2

    float* yp = d_ypart + (size_t)kcs * B_ * OUT_;
#pragma unroll
    for (int n = 0; n < 8; n++) {
        int col = n * 8 + (lane & 3) * 2;
        int r0 = rs + wid * 16 + (lane >> 2);
        if (r0 < re) {
            float2 v = make_float2(acc[n][0], acc[n][1]);
            *reinterpret_cast<float2*>(yp + (size_t)r0 * OUT_ + col) = v;
        }
        int r1 = r0 + 8;
        if (r1 < re) {
            float2 v = make_float2(acc[n][2], acc[n][3]);
            *reinterpret_cast<float2*>(yp + (size_t)r1 * OUT_ + col) = v;
        }
    }
}

// ---------------- reduce + scatter ----------------
__global__ __launch_bounds__(256) void k_reduce(const float* __restrict__ b2,
                                                float* __restrict__ y) {
    int t = blockIdx.x * 256 + threadIdx.x;
    int p = t >> 4;
    int o = (t & 15) * 4;
    int g = d_rowg[p];
    float4 acc = *reinterpret_cast<const float4*>(b2 + g * OUT_ + o);
#pragma unroll
    for (int c = 0; c < NSPLIT; c++) {
        float4 v = *reinterpret_cast<const float4*>(d_ypart + ((size_t)c * B_ + p) * OUT_ + o);
        acc.x += v.x; acc.y += v.y; acc.z += v.z; acc.w += v.w;
    }
    *reinterpret_cast<float4*>(y + (size_t)d_perm[p] * OUT_ + o) = acc;
}

// ---------------- launch ----------------
extern "C" void kernel_launch(void* const* d_in, const int* in_sizes, int n_in,
                              void* d_out, int out_size) {
    const float* x   = (const float*)d_in[0];
    const int*   gid = (const int*)  d_in[1];
    const float* W1  = (const float*)d_in[2];
    const float* b1  = (const float*)d_in[3];
    const float* W2  = (const float*)d_in[4];
    const float* b2  = (const float*)d_in[5];
    float* y = (float*)d_out;

    static bool attr_set = false;
    if (!attr_set) {
        cudaFuncSetAttribute(k_gemm1, cudaFuncAttributeMaxDynamicSharedMemorySize, SMEM1);
        cudaFuncSetAttribute(k_gemm2, cudaFuncAttributeMaxDynamicSharedMemorySize, SMEM2);
        attr_set = true;
    }

    k_count_plan<<<1, 256>>>(gid);
    k_scatter<<<B_ / 256, 256>>>(gid);
    k_convert<<<CVT_NB, 256>>>(x, W1, W2);

    dim3 g1(MAXT1, H_ / 128);
    k_gemm1<<<g1, 128, SMEM1>>>(b1);
    dim3 g2(MAXT2, NSPLIT);
    k_gemm2<<<g2, 256, SMEM2>>>();
    k_reduce<<<B_ * (OUT_ / 4) / 256, 256>>>(b2, y);
}

// round 8
// speedup vs baseline: 1.2786x; 1.2786x over previous
#include <cuda_runtime.h>
#include <cuda_bf16.h>
#include <cstdint>

#define B_   4096
#define G_   8
#define IN_  512
#define H_   1024
#define OUT_ 64

#define TM1    64
#define MAXT1  (B_ / TM1 + G_)   // 72
#define NCHUNK (H_ / 128)        // 8

// ---------------- gemm1 smem layout (per stage, bytes) ----------------
// A: 64 rows x 32k bf16, stride 80B.  B: 32 k-rows x 128n, stride 272B
#define S1_A_HI 0
#define S1_A_LO 5120
#define S1_B_HI 10240
#define S1_B_LO 18944
#define STAGE1  27648
#define SMEM1   (2 * STAGE1)     // 55296; x4 CTAs = 221184 <= 228KB/SM

// epilogue overlay (after mainloop): h tile + W2 double-buffered subchunks
#define EP_H_HI  0               // 64 rows x 272B = 17408
#define EP_H_LO  17408
#define EP_W2    34816           // 2 bufs x 9216 (hi 4608 + lo 4608) -> 53248 total

// ---------------- device scratch ----------------
__device__ int d_perm[B_];
__device__ int d_rowg[B_];
__device__ int t1_group[MAXT1], t1_start[MAXT1], t1_end[MAXT1];

__device__ __nv_bfloat16 d_xhi[(size_t)B_ * IN_];
__device__ __nv_bfloat16 d_xlo[(size_t)B_ * IN_];
__device__ __nv_bfloat16 d_w1hi[(size_t)G_ * IN_ * H_];
__device__ __nv_bfloat16 d_w1lo[(size_t)G_ * IN_ * H_];
__device__ __nv_bfloat16 d_w2hi[(size_t)G_ * H_ * OUT_];
__device__ __nv_bfloat16 d_w2lo[(size_t)G_ * H_ * OUT_];
__device__ float d_ypart[(size_t)NCHUNK * B_ * OUT_];   // 8 MB

// ---------------- asm helpers ----------------
__device__ __forceinline__ uint32_t smem_u32(const void* p) {
    uint32_t a;
    asm("{ .reg .u64 t; cvta.to.shared.u64 t, %1; cvt.u32.u64 %0, t; }" : "=r"(a) : "l"(p));
    return a;
}
__device__ __forceinline__ void cp16(uint32_t s, const void* g, int srcsz) {
    asm volatile("cp.async.cg.shared.global [%0], [%1], 16, %2;"
                 :: "r"(s), "l"(g), "r"(srcsz) : "memory");
}
#define CP_COMMIT() asm volatile("cp.async.commit_group;" ::: "memory")
#define CP_WAIT1()  asm volatile("cp.async.wait_group 1;" ::: "memory")
#define CP_WAIT0()  asm volatile("cp.async.wait_group 0;" ::: "memory")

#define LDSM_X4(r, a)                                                            \
    asm volatile("ldmatrix.sync.aligned.m8n8.x4.shared.b16 {%0,%1,%2,%3}, [%4];" \
                 : "=r"((r)[0]), "=r"((r)[1]), "=r"((r)[2]), "=r"((r)[3]) : "r"(a))
#define LDSM_X4T(r, a)                                                                 \
    asm volatile("ldmatrix.sync.aligned.m8n8.x4.trans.shared.b16 {%0,%1,%2,%3}, [%4];" \
                 : "=r"((r)[0]), "=r"((r)[1]), "=r"((r)[2]), "=r"((r)[3]) : "r"(a))

#define MMA16816(c, a, b0, b1)                                                    \
    asm volatile("mma.sync.aligned.m16n8k16.row.col.f32.bf16.bf16.f32 "           \
                 "{%0,%1,%2,%3}, {%4,%5,%6,%7}, {%8,%9}, {%0,%1,%2,%3};"          \
                 : "+f"((c)[0]), "+f"((c)[1]), "+f"((c)[2]), "+f"((c)[3])         \
                 : "r"((a)[0]), "r"((a)[1]), "r"((a)[2]), "r"((a)[3]),            \
                   "r"(b0), "r"(b1))

__device__ __forceinline__ uint32_t pack_hi2(float a, float b) {
    __nv_bfloat162 t = __floats2bfloat162_rn(a, b);
    return *reinterpret_cast<uint32_t*>(&t);
}
__device__ __forceinline__ void split8(const float* v, uint4& hi, uint4& lo) {
    float h[8], l[8];
#pragma unroll
    for (int i = 0; i < 8; i++) {
        __nv_bfloat16 bh = __float2bfloat16_rn(v[i]);
        h[i] = __bfloat162float(bh);
        l[i] = v[i] - h[i];
    }
    hi = make_uint4(pack_hi2(h[0], h[1]), pack_hi2(h[2], h[3]),
                    pack_hi2(h[4], h[5]), pack_hi2(h[6], h[7]));
    lo = make_uint4(pack_hi2(l[0], l[1]), pack_hi2(l[2], l[3]),
                    pack_hi2(l[4], l[5]), pack_hi2(l[6], l[7]));
}

// ---------------- routing: histogram + plan + scatter, ONE block ----------------
__global__ __launch_bounds__(256) void k_route(const int* __restrict__ gid) {
    __shared__ int hist[G_];
    __shared__ int cur[G_];
    int tid = threadIdx.x;
    if (tid < G_) hist[tid] = 0;
    __syncthreads();
    for (int i = tid; i < B_; i += 256) atomicAdd(&hist[gid[i]], 1);
    __syncthreads();
    if (tid == 0) {
        int offs[G_ + 1];
        offs[0] = 0;
        for (int g = 0; g < G_; g++) offs[g + 1] = offs[g] + hist[g];
        for (int g = 0; g < G_; g++) cur[g] = offs[g];
        int t = 0;
        for (int g = 0; g < G_; g++)
            for (int r = offs[g]; r < offs[g + 1]; r += TM1) {
                t1_group[t] = g; t1_start[t] = r;
                t1_end[t] = min(r + TM1, offs[g + 1]);
                t++;
            }
        for (; t < MAXT1; t++) t1_group[t] = -1;
    }
    __syncthreads();
    for (int i = tid; i < B_; i += 256) {
        int g = gid[i];
        int p = atomicAdd(&cur[g], 1);
        d_perm[p] = i;
        d_rowg[p] = g;
    }
}

// ---------------- merged converter (fp32 -> bf16 hi/lo), 16 elems/thread ----
#define CVT_XB  512
#define CVT_W1B 1024
#define CVT_W2B 128
#define CVT_NB  (CVT_XB + CVT_W1B + CVT_W2B)

__device__ __forceinline__ void cvt16(const float* __restrict__ src, size_t soff,
                                      __nv_bfloat16* dhi, __nv_bfloat16* dlo, size_t doff) {
    const float4* p = reinterpret_cast<const float4*>(src + soff);
    float4 q0 = p[0], q1 = p[1], q2 = p[2], q3 = p[3];
    float v0[8] = {q0.x, q0.y, q0.z, q0.w, q1.x, q1.y, q1.z, q1.w};
    float v1[8] = {q2.x, q2.y, q2.z, q2.w, q3.x, q3.y, q3.z, q3.w};
    uint4 h0, l0, h1, l1;
    split8(v0, h0, l0);
    split8(v1, h1, l1);
    uint4* ph = reinterpret_cast<uint4*>(dhi + doff);
    uint4* pl = reinterpret_cast<uint4*>(dlo + doff);
    ph[0] = h0; ph[1] = h1;
    pl[0] = l0; pl[1] = l1;
}

__global__ __launch_bounds__(256) void k_convert(const float* __restrict__ x,
                                                 const float* __restrict__ W1,
                                                 const float* __restrict__ W2) {
    int b = blockIdx.x;
    int tid = threadIdx.x;
    if (b < CVT_XB) {
        int u = b * 256 + tid;
        int p = u >> 5;
        int k = (u & 31) * 16;
        int src = d_perm[p];
        cvt16(x, (size_t)src * IN_ + k, d_xhi, d_xlo, (size_t)p * IN_ + k);
    } else if (b < CVT_XB + CVT_W1B) {
        size_t u = (size_t)(b - CVT_XB) * 256 + tid;
        cvt16(W1, u * 16, d_w1hi, d_w1lo, u * 16);
    } else {
        size_t u = (size_t)(b - CVT_XB - CVT_W1B) * 256 + tid;
        cvt16(W2, u * 16, d_w2hi, d_w2lo, u * 16);
    }
}

// ---------------- fused gemm: h = relu(x@W1+b1); ypart[cc] = h_chunk @ W2_chunk ----
__global__ __launch_bounds__(128, 4) void k_gemm1(const float* __restrict__ b1) {
    int tile = blockIdx.x;
    int g = t1_group[tile];
    if (g < 0) return;
    int rs = t1_start[tile], re = t1_end[tile];
    int cc = blockIdx.y;
    int n0 = cc * 128;

    extern __shared__ char sm[];
    uint32_t smb = smem_u32(sm);
    int tid = threadIdx.x;
    int lane = tid & 31;
    int wid = tid >> 5;
    int warp_m = wid >> 1, warp_n = wid & 1;

    const __nv_bfloat16* w1hi = d_w1hi + (size_t)g * IN_ * H_;
    const __nv_bfloat16* w1lo = d_w1lo + (size_t)g * IN_ * H_;
    const __nv_bfloat16* w2hi = d_w2hi + (size_t)g * H_ * OUT_;
    const __nv_bfloat16* w2lo = d_w2lo + (size_t)g * H_ * OUT_;

#define STAGE_G1(bi, ch) do {                                                    \
    int k0 = (ch) * 32;                                                          \
    uint32_t sb = smb + (bi) * STAGE1;                                           \
    _Pragma("unroll")                                                            \
    for (int j = 0; j < 2; j++) {                                                \
        int c = tid + 128 * j;                                                   \
        int row = c >> 2, seg = c & 3;                                           \
        int gr = rs + row;                                                       \
        int ok = (gr < re) ? 16 : 0;                                             \
        size_t go = (size_t)(ok ? gr : rs) * IN_ + k0 + seg * 8;                 \
        uint32_t so = row * 80 + seg * 16;                                       \
        cp16(sb + S1_A_HI + so, d_xhi + go, ok);                                 \
        cp16(sb + S1_A_LO + so, d_xlo + go, ok);                                 \
    }                                                                            \
    _Pragma("unroll")                                                            \
    for (int j = 0; j < 4; j++) {                                                \
        int c = tid + 128 * j;                                                   \
        int row = c >> 4, seg = c & 15;                                          \
        size_t go = (size_t)(k0 + row) * H_ + n0 + seg * 8;                      \
        uint32_t so = row * 272 + seg * 16;                                      \
        cp16(sb + S1_B_HI + so, w1hi + go, 16);                                  \
        cp16(sb + S1_B_LO + so, w1lo + go, 16);                                  \
    }                                                                            \
} while (0)

    float acc[2][8][4];
#pragma unroll
    for (int t = 0; t < 2; t++)
#pragma unroll
        for (int n = 0; n < 8; n++)
#pragma unroll
            for (int r = 0; r < 4; r++) acc[t][n][r] = 0.f;

    STAGE_G1(0, 0);
    CP_COMMIT();

    const int NCH = IN_ / 32;   // 16
    for (int ch = 0; ch < NCH; ch++) {
        if (ch + 1 < NCH) { STAGE_G1((ch + 1) & 1, ch + 1); CP_COMMIT(); CP_WAIT1(); }
        else CP_WAIT0();
        __syncthreads();

        uint32_t sb = smb + (ch & 1) * STAGE1;
#pragma unroll
        for (int kk = 0; kk < 2; kk++) {
            uint32_t ah[2][4], al[2][4];
#pragma unroll
            for (int t = 0; t < 2; t++) {
                uint32_t ao = (warp_m * 32 + t * 16 + (lane & 15)) * 80
                            + kk * 32 + (lane >> 4) * 16;
                LDSM_X4(ah[t], sb + S1_A_HI + ao);
                LDSM_X4(al[t], sb + S1_A_LO + ao);
            }
#pragma unroll
            for (int q = 0; q < 4; q++) {
                uint32_t bh[4], bl[4];
                uint32_t bo = (kk * 16 + (lane & 15)) * 272
                            + (warp_n * 64 + q * 16) * 2 + (lane >> 4) * 16;
                LDSM_X4T(bh, sb + S1_B_HI + bo);
                LDSM_X4T(bl, sb + S1_B_LO + bo);
                int n0q = q * 2;
#pragma unroll
                for (int t = 0; t < 2; t++) {
                    MMA16816(acc[t][n0q],     ah[t], bh[0], bh[1]);
                    MMA16816(acc[t][n0q + 1], ah[t], bh[2], bh[3]);
                }
#pragma unroll
                for (int t = 0; t < 2; t++) {
                    MMA16816(acc[t][n0q],     ah[t], bl[0], bl[1]);
                    MMA16816(acc[t][n0q + 1], ah[t], bl[2], bl[3]);
                }
#pragma unroll
                for (int t = 0; t < 2; t++) {
                    MMA16816(acc[t][n0q],     al[t], bh[0], bh[1]);
                    MMA16816(acc[t][n0q + 1], al[t], bh[2], bh[3]);
                }
            }
        }
        __syncthreads();
    }
#undef STAGE_G1

    // ======== fused layer-2 epilogue ========
    // stage W2 subchunk s (32 k-rows x 64 out) into buffer bi
#define STAGE_W2(bi, s) do {                                                     \
    int kk0 = n0 + (s) * 32;                                                     \
    uint32_t wb = smb + EP_W2 + (bi) * 9216;                                     \
    _Pragma("unroll")                                                            \
    for (int j = 0; j < 2; j++) {                                                \
        int c = tid + 128 * j;                                                   \
        int row = c >> 3, seg = c & 7;                                           \
        size_t go = (size_t)(kk0 + row) * OUT_ + seg * 8;                        \
        uint32_t so = row * 144 + seg * 16;                                      \
        cp16(wb + so, w2hi + go, 16);                                            \
        cp16(wb + 4608 + so, w2lo + go, 16);                                     \
    }                                                                            \
} while (0)

    STAGE_W2(0, 0); CP_COMMIT();
    STAGE_W2(1, 1); CP_COMMIT();

    // write h = relu(acc + b1) into smem as bf16 hi/lo (zero for invalid rows)
    const float* b1g = b1 + g * H_;
#pragma unroll
    for (int n = 0; n < 8; n++) {
        int col = warp_n * 64 + n * 8 + (lane & 3) * 2;     // local 0..127
        float bb0 = __ldg(b1g + n0 + col), bb1 = __ldg(b1g + n0 + col + 1);
#pragma unroll
        for (int t = 0; t < 2; t++) {
            int row0 = warp_m * 32 + t * 16 + (lane >> 2);  // local 0..63
            {
                bool val = (rs + row0 < re);
                float v0 = val ? fmaxf(acc[t][n][0] + bb0, 0.f) : 0.f;
                float v1 = val ? fmaxf(acc[t][n][1] + bb1, 0.f) : 0.f;
                float h0 = __bfloat162float(__float2bfloat16_rn(v0));
                float h1 = __bfloat162float(__float2bfloat16_rn(v1));
                uint32_t off = row0 * 272 + col * 2;
                *reinterpret_cast<uint32_t*>(sm + EP_H_HI + off) = pack_hi2(h0, h1);
                *reinterpret_cast<uint32_t*>(sm + EP_H_LO + off) = pack_hi2(v0 - h0, v1 - h1);
            }
            {
                int row1 = row0 + 8;
                bool val = (rs + row1 < re);
                float v0 = val ? fmaxf(acc[t][n][2] + bb0, 0.f) : 0.f;
                float v1 = val ? fmaxf(acc[t][n][3] + bb1, 0.f) : 0.f;
                float h0 = __bfloat162float(__float2bfloat16_rn(v0));
                float h1 = __bfloat162float(__float2bfloat16_rn(v1));
                uint32_t off = row1 * 272 + col * 2;
                *reinterpret_cast<uint32_t*>(sm + EP_H_HI + off) = pack_hi2(h0, h1);
                *reinterpret_cast<uint32_t*>(sm + EP_H_LO + off) = pack_hi2(v0 - h0, v1 - h1);
            }
        }
    }

    // y partial: each warp computes rows [wid*16, wid*16+16) x 64 cols
    float ya[8][4];
#pragma unroll
    for (int n = 0; n < 8; n++)
#pragma unroll
        for (int r = 0; r < 4; r++) ya[n][r] = 0.f;

    CP_WAIT1();          // subchunk 0 resident
    __syncthreads();     // h + W2 buf0 visible to all

#pragma unroll
    for (int s = 0; s < 4; s++) {
        uint32_t wb = smb + EP_W2 + (s & 1) * 9216;
#pragma unroll
        for (int j = 0; j < 2; j++) {
            uint32_t ah[4], al[4];
            uint32_t ao = (wid * 16 + (lane & 15)) * 272
                        + s * 64 + j * 32 + (lane >> 4) * 16;
            LDSM_X4(ah, smb + EP_H_HI + ao);
            LDSM_X4(al, smb + EP_H_LO + ao);
#pragma unroll
            for (int q = 0; q < 4; q++) {
                uint32_t bh[4], bl[4];
                uint32_t bo = (j * 16 + (lane & 15)) * 144 + q * 32 + (lane >> 4) * 16;
                LDSM_X4T(bh, wb + bo);
                LDSM_X4T(bl, wb + 4608 + bo);
                int nq = q * 2;
                MMA16816(ya[nq],     ah, bh[0], bh[1]);
                MMA16816(ya[nq + 1], ah, bh[2], bh[3]);
                MMA16816(ya[nq],     ah, bl[0], bl[1]);
                MMA16816(ya[nq + 1], ah, bl[2], bl[3]);
                MMA16816(ya[nq],     al, bh[0], bh[1]);
                MMA16816(ya[nq + 1], al, bh[2], bh[3]);
            }
        }
        if (s < 2) {
            __syncthreads();                 // buf (s&1) fully consumed by all warps
            if (s + 2 < 4) { STAGE_W2(s & 1, s + 2); CP_COMMIT(); }
            if (s == 0) CP_WAIT1(); else CP_WAIT0();
            __syncthreads();
        } else if (s == 2) {
            CP_WAIT0();
            __syncthreads();
        }
    }
#undef STAGE_W2

    // write 64x64 fp32 partial
    float* yp = d_ypart + (size_t)cc * B_ * OUT_;
#pragma unroll
    for (int n = 0; n < 8; n++) {
        int col = n * 8 + (lane & 3) * 2;
        int r0 = rs + wid * 16 + (lane >> 2);
        if (r0 < re) {
            float2 v = make_float2(ya[n][0], ya[n][1]);
            *reinterpret_cast<float2*>(yp + (size_t)r0 * OUT_ + col) = v;
        }
        int r1 = r0 + 8;
        if (r1 < re) {
            float2 v = make_float2(ya[n][2], ya[n][3]);
            *reinterpret_cast<float2*>(yp + (size_t)r1 * OUT_ + col) = v;
        }
    }
}

// ---------------- reduce + scatter: y[perm[p]] = b2[g] + sum_cc ypart ----------------
__global__ __launch_bounds__(256) void k_reduce(const float* __restrict__ b2,
                                                float* __restrict__ y) {
    int t = blockIdx.x * 256 + threadIdx.x;   // 65536 threads
    int p = t >> 4;
    int o = (t & 15) * 4;
    int g = d_rowg[p];
    float4 acc = *reinterpret_cast<const float4*>(b2 + g * OUT_ + o);
#pragma unroll
    for (int c = 0; c < NCHUNK; c++) {
        float4 v = *reinterpret_cast<const float4*>(d_ypart + ((size_t)c * B_ + p) * OUT_ + o);
        acc.x += v.x; acc.y += v.y; acc.z += v.z; acc.w += v.w;
    }
    *reinterpret_cast<float4*>(y + (size_t)d_perm[p] * OUT_ + o) = acc;
}

// ---------------- launch ----------------
extern "C" void kernel_launch(void* const* d_in, const int* in_sizes, int n_in,
                              void* d_out, int out_size) {
    const float* x   = (const float*)d_in[0];
    const int*   gid = (const int*)  d_in[1];
    const float* W1  = (const float*)d_in[2];
    const float* b1  = (const float*)d_in[3];
    const float* W2  = (const float*)d_in[4];
    const float* b2  = (const float*)d_in[5];
    float* y = (float*)d_out;

    static bool attr_set = false;
    if (!attr_set) {
        cudaFuncSetAttribute(k_gemm1, cudaFuncAttributeMaxDynamicSharedMemorySize, SMEM1);
        attr_set = true;
    }

    k_route<<<1, 256>>>(gid);
    k_convert<<<CVT_NB, 256>>>(x, W1, W2);
    dim3 g1(MAXT1, NCHUNK);
    k_gemm1<<<g1, 128, SMEM1>>>(b1);
    k_reduce<<<B_ * (OUT_ / 4) / 256, 256>>>(b2, y);
}